// round 2
// baseline (speedup 1.0000x reference)
#include <cuda_runtime.h>

// NeuralODE via exact linearity: x_k = (S^8)^k x0, S = Tsit5 step matrix.
// Kernel 1 (1 thread): build the 25 propagator matrices Q^k into a device
// global (+ scalar tail). Kernel 2: pure stream — one float4 of output per
// thread, fully coalesced STG.128, no shared memory, no syncs.

namespace {

constexpr int TRAJ  = 25;
constexpr int NSUB  = 8;
constexpr int BLOCK = 256;

__device__ float4 g_mats[TRAJ];   // Q^k as [a b; c d] -> (a,b,c,d)

struct M2 { float a, b, c, d; };

__device__ __forceinline__ M2 m2mul(const M2& x, const M2& y) {
    M2 r;
    r.a = fmaf(x.a, y.a, x.b * y.c);
    r.b = fmaf(x.a, y.b, x.b * y.d);
    r.c = fmaf(x.c, y.a, x.d * y.c);
    r.d = fmaf(x.c, y.b, x.d * y.d);
    return r;
}

__device__ __forceinline__ M2 stageY(float h, const M2* K, const float* c, int n) {
    M2 r = {1.f, 0.f, 0.f, 1.f};
    for (int i = 0; i < n; ++i) {
        float s = h * c[i];
        r.a = fmaf(s, K[i].a, r.a);
        r.b = fmaf(s, K[i].b, r.b);
        r.c = fmaf(s, K[i].c, r.c);
        r.d = fmaf(s, K[i].d, r.d);
    }
    return r;
}

__global__ void setup_kernel(const float* __restrict__ matrix,
                             const float* __restrict__ Tptr,
                             float* __restrict__ out,
                             long long tail_begin, long long out_elems,
                             float tailval)
{
    // --- Tsit5 tableau (Tsitouras 2011) ---
    const float A21 = 0.161f;
    const float A31 = -0.008480655492356989f, A32 = 0.335480655492357f;
    const float A41 = 2.8971530571054935f, A42 = -6.359448489975075f,
                A43 = 4.3622954328695815f;
    const float A51 = 5.325864828439257f, A52 = -11.748883564062828f,
                A53 = 7.4955393428898365f, A54 = -0.09249506636175525f;
    const float A61 = 5.86145544294642f, A62 = -12.92096931784711f,
                A63 = 8.159367898576159f, A64 = -0.071584973281401f,
                A65 = -0.028269050394068383f;
    const float B1 = 0.09646076681806523f, B2 = 0.01f,
                B3 = 0.4798896504144996f, B4 = 1.379008574103742f,
                B5 = -3.290069515436081f, B6 = 2.324710524099774f;

    const float h = 1.0f / float((TRAJ - 1) * NSUB);
    const float T = Tptr[0];
    M2 A = { T * matrix[0], T * matrix[1], T * matrix[2], T * matrix[3] };

    M2 K[6];
    K[0] = A;
    { const float c[1] = {A21};                     K[1] = m2mul(A, stageY(h, K, c, 1)); }
    { const float c[2] = {A31, A32};                K[2] = m2mul(A, stageY(h, K, c, 2)); }
    { const float c[3] = {A41, A42, A43};           K[3] = m2mul(A, stageY(h, K, c, 3)); }
    { const float c[4] = {A51, A52, A53, A54};      K[4] = m2mul(A, stageY(h, K, c, 4)); }
    { const float c[5] = {A61, A62, A63, A64, A65}; K[5] = m2mul(A, stageY(h, K, c, 5)); }
    const float bb[6] = {B1, B2, B3, B4, B5, B6};
    M2 S = stageY(h, K, bb, 6);                        // one substep
    M2 Q = m2mul(S, S); Q = m2mul(Q, Q); Q = m2mul(Q, Q);  // S^8 = save interval

    M2 P = {1.f, 0.f, 0.f, 1.f};
    #pragma unroll 1
    for (int k = 0; k < TRAJ; ++k) {
        g_mats[k] = make_float4(P.a, P.b, P.c, P.d);
        P = m2mul(Q, P);
    }

    // Scalar tail (num_steps analog), exactly representable in fp32.
    for (long long i = tail_begin; i < out_elems; ++i) out[i] = tailval;
}

// One float4 (= two float2 trajectory samples) per thread; coalesced STG.128.
__global__ void __launch_bounds__(BLOCK)
stream_kernel(const float* __restrict__ x0s,
              float4* __restrict__ out4,
              int n4)   // n4 = batch*TRAJ/2 float4 outputs
{
    const int q = blockIdx.x * BLOCK + threadIdx.x;
    if (q >= n4) return;

    const float2* __restrict__ x02 = reinterpret_cast<const float2*>(x0s);

    const int a  = 2 * q;            // first float2 sample index
    const int pa = a / 25;           // point id   (constant-div -> mul.hi)
    const int ka = a - pa * 25;      // save index

    const float2 xa = __ldg(&x02[pa]);
    const float4 ma = __ldg(&g_mats[ka]);

    int   kb = ka + 1;
    float2 xb = xa;
    if (kb == TRAJ) {                // crosses a point boundary (ka == 24)
        kb = 0;
        xb = __ldg(&x02[pa + 1]);
    }
    const float4 mb = __ldg(&g_mats[kb]);

    float4 r;
    r.x = fmaf(ma.x, xa.x, ma.y * xa.y);
    r.y = fmaf(ma.z, xa.x, ma.w * xa.y);
    r.z = fmaf(mb.x, xb.x, mb.y * xb.y);
    r.w = fmaf(mb.z, xb.x, mb.w * xb.y);
    out4[q] = r;
}

} // namespace

extern "C" void kernel_launch(void* const* d_in, const int* in_sizes, int n_in,
                              void* d_out, int out_size) {
    const float* x0s    = (const float*)d_in[0];
    const float* matrix = (const float*)d_in[1];
    const float* T      = (const float*)d_in[2];
    float* out = (float*)d_out;

    const int batch = in_sizes[0] / 2;                 // x0s is [batch,2]
    const long long n2   = (long long)batch * TRAJ;    // float2 outputs
    const int       n4   = (int)(n2 / 2);              // batch*25 is even
    const float tail = (float)((long long)batch * (TRAJ - 1) * NSUB);

    setup_kernel<<<1, 1>>>(matrix, T, out, n2 * 2, (long long)out_size, tail);

    const int grid = (n4 + BLOCK - 1) / BLOCK;
    stream_kernel<<<grid, BLOCK>>>(x0s, (float4*)out, n4);
}

// round 3
// speedup vs baseline: 1.0609x; 1.0609x over previous
#include <cuda_runtime.h>

// NeuralODE via exact linearity: x_k = (S^8)^k x0, S = Tsit5 step matrix.
// Single kernel: per-block thread-0 builds the 25 propagator matrices in
// 400B of smem; all threads then stream 4 float4 outputs each (fully
// coalesced STG.128), reading the table via LDS and x0 via broadcast loads.

namespace {

constexpr int TRAJ  = 25;
constexpr int NSUB  = 8;
constexpr int BLOCK = 256;
constexpr int ITEMS = 4;     // float4 outputs per thread

struct M2 { float a, b, c, d; };

__device__ __forceinline__ M2 m2mul(const M2& x, const M2& y) {
    M2 r;
    r.a = fmaf(x.a, y.a, x.b * y.c);
    r.b = fmaf(x.a, y.b, x.b * y.d);
    r.c = fmaf(x.c, y.a, x.d * y.c);
    r.d = fmaf(x.c, y.b, x.d * y.d);
    return r;
}

__device__ __forceinline__ M2 stageY(float h, const M2* K, const float* c, int n) {
    M2 r = {1.f, 0.f, 0.f, 1.f};
    for (int i = 0; i < n; ++i) {
        float s = h * c[i];
        r.a = fmaf(s, K[i].a, r.a);
        r.b = fmaf(s, K[i].b, r.b);
        r.c = fmaf(s, K[i].c, r.c);
        r.d = fmaf(s, K[i].d, r.d);
    }
    return r;
}

__global__ void __launch_bounds__(BLOCK)
ode_kernel(const float* __restrict__ x0s,
           const float* __restrict__ matrix,
           const float* __restrict__ Tptr,
           float4* __restrict__ out4,
           int n4, long long out_elems, float tailval)
{
    __shared__ float4 smats[TRAJ];   // Q^k as (a,b,c,d), 400 B

    if (threadIdx.x == 0) {
        // --- Tsit5 tableau (Tsitouras 2011) ---
        const float A21 = 0.161f;
        const float A31 = -0.008480655492356989f, A32 = 0.335480655492357f;
        const float A41 = 2.8971530571054935f, A42 = -6.359448489975075f,
                    A43 = 4.3622954328695815f;
        const float A51 = 5.325864828439257f, A52 = -11.748883564062828f,
                    A53 = 7.4955393428898365f, A54 = -0.09249506636175525f;
        const float A61 = 5.86145544294642f, A62 = -12.92096931784711f,
                    A63 = 8.159367898576159f, A64 = -0.071584973281401f,
                    A65 = -0.028269050394068383f;
        const float B1 = 0.09646076681806523f, B2 = 0.01f,
                    B3 = 0.4798896504144996f, B4 = 1.379008574103742f,
                    B5 = -3.290069515436081f, B6 = 2.324710524099774f;

        const float h = 1.0f / float((TRAJ - 1) * NSUB);
        const float T = Tptr[0];
        M2 A = { T * matrix[0], T * matrix[1], T * matrix[2], T * matrix[3] };

        M2 K[6];
        K[0] = A;
        { const float c[1] = {A21};                     K[1] = m2mul(A, stageY(h, K, c, 1)); }
        { const float c[2] = {A31, A32};                K[2] = m2mul(A, stageY(h, K, c, 2)); }
        { const float c[3] = {A41, A42, A43};           K[3] = m2mul(A, stageY(h, K, c, 3)); }
        { const float c[4] = {A51, A52, A53, A54};      K[4] = m2mul(A, stageY(h, K, c, 4)); }
        { const float c[5] = {A61, A62, A63, A64, A65}; K[5] = m2mul(A, stageY(h, K, c, 5)); }
        const float bb[6] = {B1, B2, B3, B4, B5, B6};
        M2 S = stageY(h, K, bb, 6);                        // one substep
        M2 Q = m2mul(S, S); Q = m2mul(Q, Q); Q = m2mul(Q, Q);  // S^8 per save

        M2 P = {1.f, 0.f, 0.f, 1.f};
        #pragma unroll 1
        for (int k = 0; k < TRAJ; ++k) {
            smats[k] = make_float4(P.a, P.b, P.c, P.d);
            P = m2mul(Q, P);
        }
    }
    __syncthreads();

    const float2* __restrict__ x02 = reinterpret_cast<const float2*>(x0s);
    const unsigned base = (unsigned)blockIdx.x * (BLOCK * ITEMS) + threadIdx.x;

    #pragma unroll
    for (int i = 0; i < ITEMS; ++i) {
        const unsigned q = base + (unsigned)i * BLOCK;
        if (q >= (unsigned)n4) break;

        const unsigned a  = 2u * q;          // first float2 sample index
        const unsigned pa = a / 25u;         // point id (mul.hi const-div)
        const int      ka = (int)(a - pa * 25u);

        const float2 xa = __ldg(&x02[pa]);
        const float4 ma = smats[ka];

        const bool cross = (ka == TRAJ - 1);
        const int  kb    = cross ? 0 : ka + 1;
        const float2 xb  = cross ? __ldg(&x02[pa + 1]) : xa;
        const float4 mb  = smats[kb];

        float4 r;
        r.x = fmaf(ma.x, xa.x, ma.y * xa.y);
        r.y = fmaf(ma.z, xa.x, ma.w * xa.y);
        r.z = fmaf(mb.x, xb.x, mb.y * xb.y);
        r.w = fmaf(mb.z, xb.x, mb.w * xb.y);
        out4[q] = r;
    }

    // Scalar tail (num_steps analog), exactly representable in fp32.
    if (blockIdx.x == 0 && threadIdx.x == 0) {
        float* out = reinterpret_cast<float*>(out4);
        for (long long i = (long long)n4 * 4; i < out_elems; ++i) out[i] = tailval;
    }
}

} // namespace

extern "C" void kernel_launch(void* const* d_in, const int* in_sizes, int n_in,
                              void* d_out, int out_size) {
    const float* x0s    = (const float*)d_in[0];
    const float* matrix = (const float*)d_in[1];
    const float* T      = (const float*)d_in[2];

    const int batch = in_sizes[0] / 2;                  // x0s is [batch,2]
    const long long n2 = (long long)batch * TRAJ;       // float2 outputs
    const int n4 = (int)(n2 / 2);                       // batch*25 is even
    const float tail = (float)((long long)batch * (TRAJ - 1) * NSUB);

    const int per_block = BLOCK * ITEMS;
    const int grid = (n4 + per_block - 1) / per_block;

    ode_kernel<<<grid, BLOCK>>>(x0s, matrix, T, (float4*)d_out,
                                n4, (long long)out_size, tail);
}

// round 4
// speedup vs baseline: 1.0703x; 1.0088x over previous
#include <cuda_runtime.h>

// NeuralODE via exact linearity: x_k = (S^8)^k x0, S = Tsit5 step matrix.
// Single kernel. Thread 0 builds the 25 propagator matrices; the table is
// then replicated into 32 per-lane copies (row stride 33 float4s) so the
// per-lane divergent LDS.128 table fetches are bank-conflict-free.
// Streaming: one float4 output per thread-item, fully coalesced STG.128.

namespace {

constexpr int TRAJ   = 25;
constexpr int NSUB   = 8;
constexpr int BLOCK  = 256;
constexpr int ITEMS  = 8;      // float4 outputs per thread
constexpr int STRIDE = 33;     // table row stride in float4 (33*4 mod 32 = 4)

struct M2 { float a, b, c, d; };

__device__ __forceinline__ M2 m2mul(const M2& x, const M2& y) {
    M2 r;
    r.a = fmaf(x.a, y.a, x.b * y.c);
    r.b = fmaf(x.a, y.b, x.b * y.d);
    r.c = fmaf(x.c, y.a, x.d * y.c);
    r.d = fmaf(x.c, y.b, x.d * y.d);
    return r;
}

__device__ __forceinline__ M2 stageY(float h, const M2* K, const float* c, int n) {
    M2 r = {1.f, 0.f, 0.f, 1.f};
    for (int i = 0; i < n; ++i) {
        float s = h * c[i];
        r.a = fmaf(s, K[i].a, r.a);
        r.b = fmaf(s, K[i].b, r.b);
        r.c = fmaf(s, K[i].c, r.c);
        r.d = fmaf(s, K[i].d, r.d);
    }
    return r;
}

__global__ void __launch_bounds__(BLOCK)
ode_kernel(const float* __restrict__ x0s,
           const float* __restrict__ matrix,
           const float* __restrict__ Tptr,
           float4* __restrict__ out4,
           int n4, long long out_elems, float tailval)
{
    __shared__ float4 tbl[32 * STRIDE];   // 32 per-lane copies, 16.9 KB

    if (threadIdx.x == 0) {
        // --- Tsit5 tableau (Tsitouras 2011) ---
        const float A21 = 0.161f;
        const float A31 = -0.008480655492356989f, A32 = 0.335480655492357f;
        const float A41 = 2.8971530571054935f, A42 = -6.359448489975075f,
                    A43 = 4.3622954328695815f;
        const float A51 = 5.325864828439257f, A52 = -11.748883564062828f,
                    A53 = 7.4955393428898365f, A54 = -0.09249506636175525f;
        const float A61 = 5.86145544294642f, A62 = -12.92096931784711f,
                    A63 = 8.159367898576159f, A64 = -0.071584973281401f,
                    A65 = -0.028269050394068383f;
        const float B1 = 0.09646076681806523f, B2 = 0.01f,
                    B3 = 0.4798896504144996f, B4 = 1.379008574103742f,
                    B5 = -3.290069515436081f, B6 = 2.324710524099774f;

        const float h = 1.0f / float((TRAJ - 1) * NSUB);
        const float T = Tptr[0];
        M2 A = { T * matrix[0], T * matrix[1], T * matrix[2], T * matrix[3] };

        M2 K[6];
        K[0] = A;
        { const float c[1] = {A21};                     K[1] = m2mul(A, stageY(h, K, c, 1)); }
        { const float c[2] = {A31, A32};                K[2] = m2mul(A, stageY(h, K, c, 2)); }
        { const float c[3] = {A41, A42, A43};           K[3] = m2mul(A, stageY(h, K, c, 3)); }
        { const float c[4] = {A51, A52, A53, A54};      K[4] = m2mul(A, stageY(h, K, c, 4)); }
        { const float c[5] = {A61, A62, A63, A64, A65}; K[5] = m2mul(A, stageY(h, K, c, 5)); }
        const float bb[6] = {B1, B2, B3, B4, B5, B6};
        M2 S = stageY(h, K, bb, 6);                        // one substep
        M2 Q = m2mul(S, S); Q = m2mul(Q, Q); Q = m2mul(Q, Q);  // S^8 per save

        M2 P = {1.f, 0.f, 0.f, 1.f};
        #pragma unroll 1
        for (int k = 0; k < TRAJ; ++k) {
            tbl[k] = make_float4(P.a, P.b, P.c, P.d);   // copy 0
            P = m2mul(Q, P);
        }
    }
    __syncthreads();

    // Replicate copy 0 into the other 31 lane-copies (775 float4 writes).
    for (int i = threadIdx.x; i < 31 * TRAJ; i += BLOCK) {
        const int cp = 1 + i / TRAJ;
        const int k  = i - (cp - 1) * TRAJ;
        tbl[cp * STRIDE + k] = tbl[k];
    }
    __syncthreads();

    const float4* __restrict__ mytbl = tbl + (threadIdx.x & 31) * STRIDE;
    const float2* __restrict__ x02   = reinterpret_cast<const float2*>(x0s);
    const unsigned base = (unsigned)blockIdx.x * (BLOCK * ITEMS) + threadIdx.x;

    #pragma unroll
    for (int i = 0; i < ITEMS; ++i) {
        const unsigned q = base + (unsigned)i * BLOCK;
        if (q >= (unsigned)n4) break;

        const unsigned a  = 2u * q;          // first float2 sample index
        const unsigned pa = a / 25u;         // point id (mul.hi const-div)
        const int      ka = (int)(a - pa * 25u);

        const float2 xa = __ldg(&x02[pa]);
        const float4 ma = mytbl[ka];

        const bool  cross = (ka == TRAJ - 1);
        const int   kb    = cross ? 0 : ka + 1;
        const float2 xb   = cross ? __ldg(&x02[pa + 1]) : xa;
        const float4 mb   = mytbl[kb];

        float4 r;
        r.x = fmaf(ma.x, xa.x, ma.y * xa.y);
        r.y = fmaf(ma.z, xa.x, ma.w * xa.y);
        r.z = fmaf(mb.x, xb.x, mb.y * xb.y);
        r.w = fmaf(mb.z, xb.x, mb.w * xb.y);
        out4[q] = r;
    }

    // Scalar tail (num_steps analog), exactly representable in fp32.
    if (blockIdx.x == 0 && threadIdx.x == 0) {
        float* out = reinterpret_cast<float*>(out4);
        for (long long i = (long long)n4 * 4; i < out_elems; ++i) out[i] = tailval;
    }
}

} // namespace

extern "C" void kernel_launch(void* const* d_in, const int* in_sizes, int n_in,
                              void* d_out, int out_size) {
    const float* x0s    = (const float*)d_in[0];
    const float* matrix = (const float*)d_in[1];
    const float* T      = (const float*)d_in[2];

    const int batch = in_sizes[0] / 2;                  // x0s is [batch,2]
    const long long n2 = (long long)batch * TRAJ;       // float2 outputs
    const int n4 = (int)(n2 / 2);                       // batch*25 is even
    const float tail = (float)((long long)batch * (TRAJ - 1) * NSUB);

    const int per_block = BLOCK * ITEMS;
    const int grid = (n4 + per_block - 1) / per_block;

    ode_kernel<<<grid, BLOCK>>>(x0s, matrix, T, (float4*)d_out,
                                n4, (long long)out_size, tail);
}

// round 5
// speedup vs baseline: 1.0714x; 1.0011x over previous
#include <cuda_runtime.h>

// NeuralODE via exact linearity: x_k = Q^k x0, Q = (Tsit5 substep matrix)^8.
// All propagators are powers of one 2x2 Q and commute, so each thread carries
// P = Q^{ka} in REGISTERS and updates it per item with uniform Q^{+12} or
// Q^{-13} (item stride 512 samples = 20 points + 12). Only ONE divergent
// shared-memory table fetch per thread; the streaming loop is LDG + FMA + STG.

namespace {

constexpr int TRAJ  = 25;
constexpr int NSUB  = 8;
constexpr int BLOCK = 256;
constexpr int ITEMS = 8;     // float4 outputs per thread; item stride = BLOCK

struct M2 { float a, b, c, d; };

__device__ __forceinline__ M2 m2mul(const M2& x, const M2& y) {
    M2 r;
    r.a = fmaf(x.a, y.a, x.b * y.c);
    r.b = fmaf(x.a, y.b, x.b * y.d);
    r.c = fmaf(x.c, y.a, x.d * y.c);
    r.d = fmaf(x.c, y.b, x.d * y.d);
    return r;
}

__device__ __forceinline__ M2 stageY(float h, const M2* K, const float* c, int n) {
    M2 r = {1.f, 0.f, 0.f, 1.f};
    for (int i = 0; i < n; ++i) {
        float s = h * c[i];
        r.a = fmaf(s, K[i].a, r.a);
        r.b = fmaf(s, K[i].b, r.b);
        r.c = fmaf(s, K[i].c, r.c);
        r.d = fmaf(s, K[i].d, r.d);
    }
    return r;
}

__global__ void __launch_bounds__(BLOCK)
ode_kernel(const float* __restrict__ x0s,
           const float* __restrict__ matrix,
           const float* __restrict__ Tptr,
           float4* __restrict__ out4,
           int n4, long long out_elems, float tailval)
{
    __shared__ float4 tbl[TRAJ + 3];   // [0..24]=Q^k, [25]=Q, [26]=Q^12, [27]=Q^-13

    if (threadIdx.x == 0) {
        // --- Tsit5 tableau (Tsitouras 2011) ---
        const float A21 = 0.161f;
        const float A31 = -0.008480655492356989f, A32 = 0.335480655492357f;
        const float A41 = 2.8971530571054935f, A42 = -6.359448489975075f,
                    A43 = 4.3622954328695815f;
        const float A51 = 5.325864828439257f, A52 = -11.748883564062828f,
                    A53 = 7.4955393428898365f, A54 = -0.09249506636175525f;
        const float A61 = 5.86145544294642f, A62 = -12.92096931784711f,
                    A63 = 8.159367898576159f, A64 = -0.071584973281401f,
                    A65 = -0.028269050394068383f;
        const float B1 = 0.09646076681806523f, B2 = 0.01f,
                    B3 = 0.4798896504144996f, B4 = 1.379008574103742f,
                    B5 = -3.290069515436081f, B6 = 2.324710524099774f;

        const float h = 1.0f / float((TRAJ - 1) * NSUB);
        const float T = Tptr[0];
        M2 A = { T * matrix[0], T * matrix[1], T * matrix[2], T * matrix[3] };

        M2 K[6];
        K[0] = A;
        { const float c[1] = {A21};                     K[1] = m2mul(A, stageY(h, K, c, 1)); }
        { const float c[2] = {A31, A32};                K[2] = m2mul(A, stageY(h, K, c, 2)); }
        { const float c[3] = {A41, A42, A43};           K[3] = m2mul(A, stageY(h, K, c, 3)); }
        { const float c[4] = {A51, A52, A53, A54};      K[4] = m2mul(A, stageY(h, K, c, 4)); }
        { const float c[5] = {A61, A62, A63, A64, A65}; K[5] = m2mul(A, stageY(h, K, c, 5)); }
        const float bb[6] = {B1, B2, B3, B4, B5, B6};
        M2 S = stageY(h, K, bb, 6);                         // one substep
        M2 Q = m2mul(S, S); Q = m2mul(Q, Q); Q = m2mul(Q, Q);   // S^8

        M2 P = {1.f, 0.f, 0.f, 1.f};
        #pragma unroll 1
        for (int k = 0; k < TRAJ; ++k) {
            tbl[k] = make_float4(P.a, P.b, P.c, P.d);
            P = m2mul(Q, P);
        }
        M2 Q2  = m2mul(Q, Q);
        M2 Q4  = m2mul(Q2, Q2);
        M2 Q8  = m2mul(Q4, Q4);
        M2 Q12 = m2mul(Q8, Q4);
        M2 Q13 = m2mul(Q12, Q);
        const float invdet = 1.0f / (Q13.a * Q13.d - Q13.b * Q13.c);
        M2 QW = {  Q13.d * invdet, -Q13.b * invdet,
                  -Q13.c * invdet,  Q13.a * invdet };   // Q^-13

        tbl[25] = make_float4(Q.a, Q.b, Q.c, Q.d);
        tbl[26] = make_float4(Q12.a, Q12.b, Q12.c, Q12.d);
        tbl[27] = make_float4(QW.a, QW.b, QW.c, QW.d);
    }
    __syncthreads();

    // Uniform matrices (broadcast LDS, then registers).
    const float4 fQ  = tbl[25];
    const float4 fQF = tbl[26];
    const float4 fQW = tbl[27];

    const float2* __restrict__ x02 = reinterpret_cast<const float2*>(x0s);

    const int q0 = blockIdx.x * (BLOCK * ITEMS) + threadIdx.x;
    int a = 2 * q0;                          // first sample index (fits int32)
    unsigned pa = (unsigned)a / 25u;         // point id
    int ka = a - (int)(pa * 25u);            // save index

    float4 P = tbl[ka];                      // Q^{ka}: the ONLY divergent LDS

    #pragma unroll
    for (int i = 0; i < ITEMS; ++i) {
        const int q = q0 + i * BLOCK;
        if (q >= n4) break;

        const float2 xa = x02[pa];

        float4 r;
        r.x = fmaf(P.x, xa.x, P.y * xa.y);
        r.y = fmaf(P.z, xa.x, P.w * xa.y);

        if (ka == TRAJ - 1) {                // crossing: second sample is x0 of next point
            const float2 xb = x02[pa + 1];
            r.z = xb.x;
            r.w = xb.y;
        } else {
            r.z = fmaf(fQ.x, r.x, fQ.y * r.y);
            r.w = fmaf(fQ.z, r.x, fQ.w * r.y);
        }
        out4[q] = r;

        // Advance to next item: ka += 12 (mod 25); P *= Q^12 or Q^-13 (commute).
        const bool wrap = (ka >= 13);
        const float4 U = wrap ? fQW : fQF;
        float4 Pn;
        Pn.x = fmaf(P.x, U.x, P.y * U.z);
        Pn.y = fmaf(P.x, U.y, P.y * U.w);
        Pn.z = fmaf(P.z, U.x, P.w * U.z);
        Pn.w = fmaf(P.z, U.y, P.w * U.w);
        P = Pn;
        ka += wrap ? -13 : 12;
        pa += wrap ? 21u : 20u;
    }

    // Scalar tail (num_steps analog), exactly representable in fp32.
    if (blockIdx.x == 0 && threadIdx.x == 0) {
        float* out = reinterpret_cast<float*>(out4);
        for (long long i = (long long)n4 * 4; i < out_elems; ++i) out[i] = tailval;
    }
}

} // namespace

extern "C" void kernel_launch(void* const* d_in, const int* in_sizes, int n_in,
                              void* d_out, int out_size) {
    const float* x0s    = (const float*)d_in[0];
    const float* matrix = (const float*)d_in[1];
    const float* T      = (const float*)d_in[2];

    const int batch = in_sizes[0] / 2;                  // x0s is [batch,2]
    const long long n2 = (long long)batch * TRAJ;       // float2 outputs
    const int n4 = (int)(n2 / 2);                       // batch*25 is even
    const float tail = (float)((long long)batch * (TRAJ - 1) * NSUB);

    const int per_block = BLOCK * ITEMS;
    const int grid = (n4 + per_block - 1) / per_block;

    ode_kernel<<<grid, BLOCK>>>(x0s, matrix, T, (float4*)d_out,
                                n4, (long long)out_size, tail);
}

// round 6
// speedup vs baseline: 1.2880x; 1.2021x over previous
#include <cuda_runtime.h>

// NeuralODE via exact linearity: x_k = Q^k x0, Q = (Tsit5 substep)^8.
// R1-style staged burst-flush (empirically the fastest store pattern), but
// with PHASED staging so smem stays 25.6KB while BLOCK=256 -> 2048 thr/SM
// (100% occupancy, double R1). Phase h: threads [h*128,(h+1)*128) compute
// their 25 samples into smem; then all 256 threads flush the contiguous
// 25.6KB region as float4 (LDS.128 + STG.128, fully coalesced).

namespace {

constexpr int TRAJ  = 25;
constexpr int NSUB  = 8;
constexpr int BLOCK = 256;
constexpr int HALF  = 128;                  // points staged per phase
constexpr int F4_PER_PHASE = HALF * TRAJ / 2;   // 1600 float4s

struct M2 { float a, b, c, d; };

__device__ __forceinline__ M2 m2mul(const M2& x, const M2& y) {
    M2 r;
    r.a = fmaf(x.a, y.a, x.b * y.c);
    r.b = fmaf(x.a, y.b, x.b * y.d);
    r.c = fmaf(x.c, y.a, x.d * y.c);
    r.d = fmaf(x.c, y.b, x.d * y.d);
    return r;
}

__device__ __forceinline__ M2 stageY(float h, const M2* K, const float* c, int n) {
    M2 r = {1.f, 0.f, 0.f, 1.f};
    for (int i = 0; i < n; ++i) {
        float s = h * c[i];
        r.a = fmaf(s, K[i].a, r.a);
        r.b = fmaf(s, K[i].b, r.b);
        r.c = fmaf(s, K[i].c, r.c);
        r.d = fmaf(s, K[i].d, r.d);
    }
    return r;
}

__global__ void __launch_bounds__(BLOCK)
ode_kernel(const float* __restrict__ x0s,
           const float* __restrict__ matrix,
           const float* __restrict__ Tptr,
           float4* __restrict__ out4,
           int batch, int n4, long long out_elems, float tailval)
{
    __shared__ float4 mats[TRAJ];                 // Q^k table, 400 B
    __shared__ float2 stage[HALF * TRAJ];         // 25.6 KB phase tile

    if (threadIdx.x == 0) {
        // --- Tsit5 tableau (Tsitouras 2011) ---
        const float A21 = 0.161f;
        const float A31 = -0.008480655492356989f, A32 = 0.335480655492357f;
        const float A41 = 2.8971530571054935f, A42 = -6.359448489975075f,
                    A43 = 4.3622954328695815f;
        const float A51 = 5.325864828439257f, A52 = -11.748883564062828f,
                    A53 = 7.4955393428898365f, A54 = -0.09249506636175525f;
        const float A61 = 5.86145544294642f, A62 = -12.92096931784711f,
                    A63 = 8.159367898576159f, A64 = -0.071584973281401f,
                    A65 = -0.028269050394068383f;
        const float B1 = 0.09646076681806523f, B2 = 0.01f,
                    B3 = 0.4798896504144996f, B4 = 1.379008574103742f,
                    B5 = -3.290069515436081f, B6 = 2.324710524099774f;

        const float h = 1.0f / float((TRAJ - 1) * NSUB);
        const float T = Tptr[0];
        M2 A = { T * matrix[0], T * matrix[1], T * matrix[2], T * matrix[3] };

        M2 K[6];
        K[0] = A;
        { const float c[1] = {A21};                     K[1] = m2mul(A, stageY(h, K, c, 1)); }
        { const float c[2] = {A31, A32};                K[2] = m2mul(A, stageY(h, K, c, 2)); }
        { const float c[3] = {A41, A42, A43};           K[3] = m2mul(A, stageY(h, K, c, 3)); }
        { const float c[4] = {A51, A52, A53, A54};      K[4] = m2mul(A, stageY(h, K, c, 4)); }
        { const float c[5] = {A61, A62, A63, A64, A65}; K[5] = m2mul(A, stageY(h, K, c, 5)); }
        const float bb[6] = {B1, B2, B3, B4, B5, B6};
        M2 S = stageY(h, K, bb, 6);                          // one substep
        M2 Q = m2mul(S, S); Q = m2mul(Q, Q); Q = m2mul(Q, Q); // S^8

        M2 P = {1.f, 0.f, 0.f, 1.f};
        #pragma unroll 1
        for (int k = 0; k < TRAJ; ++k) {
            mats[k] = make_float4(P.a, P.b, P.c, P.d);
            P = m2mul(Q, P);
        }
    }
    __syncthreads();

    const float2* __restrict__ x02 = reinterpret_cast<const float2*>(x0s);
    const float4* __restrict__ st4 = reinterpret_cast<const float4*>(stage);
    const int half_id = threadIdx.x >> 7;        // 0 or 1
    const int lane128 = threadIdx.x & (HALF - 1);

    #pragma unroll 1
    for (int ph = 0; ph < 2; ++ph) {
        // --- compute phase: 128 of the 256 threads stage their point ---
        if (half_id == ph) {
            const int point = blockIdx.x * BLOCK + ph * HALF + lane128;
            float2 xy = make_float2(0.f, 0.f);
            if (point < batch) xy = x02[point];
            #pragma unroll
            for (int k = 0; k < TRAJ; ++k) {
                const float4 m = mats[k];     // uniform k -> LDS broadcast
                stage[lane128 * TRAJ + k] =
                    make_float2(fmaf(m.x, xy.x, m.y * xy.y),
                                fmaf(m.z, xy.x, m.w * xy.y));
            }
        }
        __syncthreads();

        // --- flush phase: all 256 threads, contiguous float4 burst ---
        const int base4 = blockIdx.x * (2 * F4_PER_PHASE) + ph * F4_PER_PHASE;
        #pragma unroll
        for (int i = 0; i < F4_PER_PHASE / BLOCK + 1; ++i) {
            const int j = i * BLOCK + threadIdx.x;
            const int idx = base4 + j;
            if (j < F4_PER_PHASE && idx < n4) out4[idx] = st4[j];
        }
        __syncthreads();
    }

    // Scalar tail (num_steps analog), exactly representable in fp32.
    if (blockIdx.x == 0 && threadIdx.x == 0) {
        float* out = reinterpret_cast<float*>(out4);
        for (long long i = (long long)n4 * 4; i < out_elems; ++i) out[i] = tailval;
    }
}

} // namespace

extern "C" void kernel_launch(void* const* d_in, const int* in_sizes, int n_in,
                              void* d_out, int out_size) {
    const float* x0s    = (const float*)d_in[0];
    const float* matrix = (const float*)d_in[1];
    const float* T      = (const float*)d_in[2];

    const int batch = in_sizes[0] / 2;                 // x0s is [batch,2]
    const long long n2 = (long long)batch * TRAJ;      // float2 outputs
    const int n4 = (int)(n2 / 2);                      // batch*25 even
    const float tail = (float)((long long)batch * (TRAJ - 1) * NSUB);

    const int grid = (batch + BLOCK - 1) / BLOCK;
    ode_kernel<<<grid, BLOCK>>>(x0s, matrix, T, (float4*)d_out,
                                batch, n4, (long long)out_size, tail);
}